// round 5
// baseline (speedup 1.0000x reference)
#include <cuda_runtime.h>
#include <cuda_fp16.h>
#include <cstdint>

// Problem constants
#define Bb 2
#define Tt 4096
#define Dd 4096
#define Hh 32
#define HKV 8
#define DH 128
#define Mrows 8192         // B*T
#define Ncols 6144         // D + 2*HKV*DH
#define Kdim 4096

// GEMM tiling (fp16 legacy mma + ldmatrix), 128 threads = 4 warps, warp tile 64x64
#define BM 128
#define BN 128
#define BK 64
#define NKITER (Kdim / BK)            // 64
#define STAGES 3
#define A_STAGE_BYTES (BM * BK * 2)   // 16384
#define B_STAGE_BYTES (BN * BK * 2)   // 16384
#define SMEM_BYTES (STAGES * (A_STAGE_BYTES + B_STAGE_BYTES))  // 98304

#define MT (Mrows / BM)   // 64
#define NT (Ncols / BN)   // 48
#define GM 16

// Scratch device globals
__device__ __half g_Ch[(size_t)Mrows * Ncols];        // GEMM result fp16 (~100 MB)
__device__ __half g_xh[(size_t)Mrows * Kdim];         // fp16 x, [M,K] row-major
__device__ __half g_Wth[(size_t)Ncols * Kdim];        // fp16 W^T, [N,K] row-major
__device__ float2 g_tab[Tt * (DH / 2)];               // RoPE (cos,sin) table

// ---------------------------------------------------------------------------
// PTX helpers
// ---------------------------------------------------------------------------
__device__ __forceinline__ void cp_async16(uint32_t dst, const void* src) {
    asm volatile("cp.async.cg.shared.global [%0], [%1], 16;\n" :: "r"(dst), "l"(src));
}
__device__ __forceinline__ void cp_commit() {
    asm volatile("cp.async.commit_group;\n" ::: "memory");
}
__device__ __forceinline__ void cp_wait1() {
    asm volatile("cp.async.wait_group 1;\n" ::: "memory");
}
__device__ __forceinline__ void ldmatrix_x4(uint32_t r[4], uint32_t addr) {
    asm volatile("ldmatrix.sync.aligned.m8n8.x4.shared.b16 {%0,%1,%2,%3}, [%4];"
                 : "=r"(r[0]), "=r"(r[1]), "=r"(r[2]), "=r"(r[3]) : "r"(addr));
}
__device__ __forceinline__ void mma_f16(float c[4], const uint32_t a[4], const uint32_t b[2]) {
    asm volatile(
        "mma.sync.aligned.m16n8k16.row.col.f32.f16.f16.f32 "
        "{%0,%1,%2,%3}, {%4,%5,%6,%7}, {%8,%9}, {%0,%1,%2,%3};"
        : "+f"(c[0]), "+f"(c[1]), "+f"(c[2]), "+f"(c[3])
        : "r"(a[0]), "r"(a[1]), "r"(a[2]), "r"(a[3]), "r"(b[0]), "r"(b[1]));
}
__device__ __forceinline__ uint32_t swz128(uint32_t off) {
    return off ^ ((off >> 3) & 0x70);
}

// ---------------------------------------------------------------------------
// Kernel 1: RoPE cos/sin table
// ---------------------------------------------------------------------------
__global__ void rope_table_kernel() {
    int idx = blockIdx.x * blockDim.x + threadIdx.x;
    if (idx >= Tt * 64) return;
    int t = idx >> 6;
    int j = idx & 63;
    double inv = exp2(-((double)(2 * j)) * (1.0 / 128.0) * 13.287712379549449);
    double a = (double)t * inv;
    double red = remainder(a, 6.283185307179586477);
    float s, c;
    sincosf((float)red, &s, &c);
    g_tab[idx] = make_float2(c, s);
}

// ---------------------------------------------------------------------------
// Kernel 2a: convert x -> fp16
// ---------------------------------------------------------------------------
__global__ void convert_x_kernel(const float* __restrict__ x) {
    size_t i = (size_t)blockIdx.x * blockDim.x + threadIdx.x;   // float4 index
    const size_t N4 = (size_t)Mrows * Kdim / 4;
    if (i >= N4) return;
    float4 v = reinterpret_cast<const float4*>(x)[i];
    __half2 h0 = make_half2(__float2half_rn(v.x), __float2half_rn(v.y));
    __half2 h1 = make_half2(__float2half_rn(v.z), __float2half_rn(v.w));
    reinterpret_cast<__half2*>(g_xh)[2 * i]     = h0;
    reinterpret_cast<__half2*>(g_xh)[2 * i + 1] = h1;
}

// ---------------------------------------------------------------------------
// Kernel 2b: transpose + convert [Wq|Wk|Wv] -> fp16 g_Wth[n][k]
// ---------------------------------------------------------------------------
__global__ void convert_w_kernel(const float* __restrict__ Wq,
                                 const float* __restrict__ Wk,
                                 const float* __restrict__ Wv) {
    __shared__ __half tile[32][34];
    const int n0 = blockIdx.x * 32;
    const int k0 = blockIdx.y * 32;
    #pragma unroll
    for (int i = 0; i < 4; i++) {
        int k = k0 + threadIdx.y + i * 8;
        int n = n0 + threadIdx.x;
        float v;
        if (n < 4096)       v = Wq[(size_t)k * 4096 + n];
        else if (n < 5120)  v = Wk[(size_t)k * 1024 + (n - 4096)];
        else                v = Wv[(size_t)k * 1024 + (n - 5120)];
        tile[threadIdx.y + i * 8][threadIdx.x] = __float2half_rn(v);
    }
    __syncthreads();
    #pragma unroll
    for (int i = 0; i < 4; i++) {
        int n = n0 + threadIdx.y + i * 8;
        int k = k0 + threadIdx.x;
        g_Wth[(size_t)n * Kdim + k] = tile[threadIdx.x][threadIdx.y + i * 8];
    }
}

// ---------------------------------------------------------------------------
// Kernel 3: fp16 GEMM  C = g_xh @ g_Wth^T (ldmatrix + HMMA)
// 3072 CTAs (64M x 48N, GROUP_M=16), 128 thr = 4 warps (2M x 2N), warp 64x64
// ---------------------------------------------------------------------------
__global__ __launch_bounds__(128, 2) void gemm_kernel() {
    extern __shared__ char smem[];
    const uint32_t smem_base = (uint32_t)__cvta_generic_to_shared(smem);
    const uint32_t a_base = smem_base;                          // 3 x 16KB
    const uint32_t b_base = smem_base + STAGES * A_STAGE_BYTES; // 3 x 16KB

    int gid = blockIdx.x;
    int group = gid / (GM * NT);
    int rem = gid % (GM * NT);
    const int mt = group * GM + (rem % GM);
    const int nt = rem / GM;
    const int m0 = mt * BM;
    const int n0 = nt * BN;

    const int tid = threadIdx.x;
    const int lane = tid & 31;
    const int wid = tid >> 5;
    const int warp_m = wid & 1;   // 0..1, 64 rows each
    const int warp_n = wid >> 1;  // 0..1, 64 cols each

    float acc[4][8][4];
    #pragma unroll
    for (int i = 0; i < 4; i++)
        #pragma unroll
        for (int j = 0; j < 8; j++)
            #pragma unroll
            for (int r = 0; r < 4; r++)
                acc[i][j][r] = 0.0f;

    auto issue = [&](int ktile, int slot) {
        const int k0 = ktile * BK;
        const uint32_t a_dst = a_base + slot * A_STAGE_BYTES;
        const uint32_t b_dst = b_base + slot * B_STAGE_BYTES;
        const __half* a_src = g_xh + (size_t)m0 * Kdim + k0;
        const __half* b_src = g_Wth + (size_t)n0 * Kdim + k0;
        #pragma unroll
        for (int i = 0; i < 8; i++) {          // A: 1024 16B-chunks / 128 thr
            int idx = tid + i * 128;
            int row = idx >> 3;                // 0..127
            int kq = idx & 7;
            cp_async16(a_dst + swz128(row * 128 + kq * 16),
                       a_src + (size_t)row * Kdim + kq * 8);
        }
        #pragma unroll
        for (int i = 0; i < 8; i++) {          // B: 1024 16B-chunks / 128 thr
            int idx = tid + i * 128;
            int row = idx >> 3;
            int kq = idx & 7;
            cp_async16(b_dst + swz128(row * 128 + kq * 16),
                       b_src + (size_t)row * Kdim + kq * 8);
        }
        cp_commit();
    };

    issue(0, 0);
    issue(1, 1);

    // ldmatrix lane addressing
    const int a_row = warp_m * 64 + (lane & 15);                      // + mi*16
    const int a_ch  = lane >> 4;                                      // + ks*2
    const int b_row = warp_n * 64 + (lane & 7) + ((lane >> 4) << 3);  // + ng*16
    const int b_ch  = (lane >> 3) & 1;                                // + ks*2

    #pragma unroll 1
    for (int it = 0; it < NKITER; it++) {
        const int slot = it % STAGES;
        cp_wait1();
        __syncthreads();

        {
            int lt = it + 2;
            if (lt > NKITER - 1) lt = NKITER - 1;
            issue(lt, (it + 2) % STAGES);
        }

        const uint32_t A_s = a_base + slot * A_STAGE_BYTES;
        const uint32_t B_s = b_base + slot * B_STAGE_BYTES;

        #pragma unroll
        for (int ks = 0; ks < 4; ks++) {
            uint32_t a[4][4], b[4][4];
            #pragma unroll
            for (int mi = 0; mi < 4; mi++)
                ldmatrix_x4(a[mi], A_s + swz128((a_row + mi * 16) * 128 +
                                                (ks * 2 + a_ch) * 16));
            #pragma unroll
            for (int ng = 0; ng < 4; ng++)
                ldmatrix_x4(b[ng], B_s + swz128((b_row + ng * 16) * 128 +
                                                (ks * 2 + b_ch) * 16));
            #pragma unroll
            for (int mi = 0; mi < 4; mi++) {
                #pragma unroll
                for (int ng = 0; ng < 4; ng++) {
                    mma_f16(acc[mi][ng * 2],     a[mi], &b[ng][0]);
                    mma_f16(acc[mi][ng * 2 + 1], a[mi], &b[ng][2]);
                }
            }
        }
    }

    // write accumulators to fp16 scratch C
    const int nbase = n0 + warp_n * 64;
    #pragma unroll
    for (int mi = 0; mi < 4; mi++) {
        int row = m0 + warp_m * 64 + mi * 16 + (lane >> 2);
        #pragma unroll
        for (int ni = 0; ni < 8; ni++) {
            int col = nbase + ni * 8 + (lane & 3) * 2;
            __half* p = g_Ch + (size_t)row * Ncols + col;
            *reinterpret_cast<__half2*>(p) =
                make_half2(__float2half_rn(acc[mi][ni][0]), __float2half_rn(acc[mi][ni][1]));
            *reinterpret_cast<__half2*>(p + (size_t)8 * Ncols) =
                make_half2(__float2half_rn(acc[mi][ni][2]), __float2half_rn(acc[mi][ni][3]));
        }
    }
}

// ---------------------------------------------------------------------------
// Kernel 4: per-token epilogue — rmsnorm(q,k), gamma, RoPE, transpose, repeat
// ---------------------------------------------------------------------------
__global__ __launch_bounds__(256) void epilogue_kernel(
    const float* __restrict__ gq,
    const float* __restrict__ gk,
    float* __restrict__ out)
{
    const int bt = blockIdx.x;
    const int b = bt >> 12;
    const int t = bt & 4095;
    const __half* row = g_Ch + (size_t)bt * Ncols;
    const int tid = threadIdx.x;

    float2 qv[8], kv2[2], vvp[2];
    float ssq_q = 0.0f, ssq_k = 0.0f;
    #pragma unroll
    for (int i = 0; i < 8; i++) {
        int p = tid + i * 256;
        qv[i] = __half22float2(*reinterpret_cast<const __half2*>(row + 2 * p));
        ssq_q += qv[i].x * qv[i].x + qv[i].y * qv[i].y;
    }
    #pragma unroll
    for (int i = 0; i < 2; i++) {
        int p = tid + i * 256;
        kv2[i] = __half22float2(*reinterpret_cast<const __half2*>(row + 4096 + 2 * p));
        ssq_k += kv2[i].x * kv2[i].x + kv2[i].y * kv2[i].y;
    }
    {
        const __half2* vp = reinterpret_cast<const __half2*>(row + 5120 + tid * 4);
        vvp[0] = __half22float2(vp[0]);
        vvp[1] = __half22float2(vp[1]);
    }

    __shared__ float redq[256], redk[256];
    redq[tid] = ssq_q;
    redk[tid] = ssq_k;
    __syncthreads();
    #pragma unroll
    for (int s = 128; s > 0; s >>= 1) {
        if (tid < s) {
            redq[tid] += redq[tid + s];
            redk[tid] += redk[tid + s];
        }
        __syncthreads();
    }
    const float rs_q = rsqrtf(redq[0] * (1.0f / 4096.0f) + 1e-5f);
    const float rs_k = rsqrtf(redk[0] * (1.0f / 1024.0f) + 1e-5f);

    const float2* tab = g_tab + t * 64;
    float* outq = out;
    float* outk = out + (size_t)33554432;
    float* outv = out + (size_t)67108864;

    #pragma unroll
    for (int i = 0; i < 8; i++) {
        int p = tid + i * 256;
        int h = p >> 6;
        int j = p & 63;
        float2 cs = tab[j];
        float x1 = qv[i].x * rs_q * gq[2 * p];
        float x2 = qv[i].y * rs_q * gq[2 * p + 1];
        float2 r = make_float2(x1 * cs.x - x2 * cs.y, x1 * cs.y + x2 * cs.x);
        *reinterpret_cast<float2*>(
            outq + (((size_t)(b * Hh + h) * Tt + t) * DH + 2 * j)) = r;
    }
    #pragma unroll
    for (int i = 0; i < 2; i++) {
        int p = tid + i * 256;
        int kh = p >> 6;
        int j = p & 63;
        float2 cs = tab[j];
        float x1 = kv2[i].x * rs_k * gk[2 * p];
        float x2 = kv2[i].y * rs_k * gk[2 * p + 1];
        float2 r = make_float2(x1 * cs.x - x2 * cs.y, x1 * cs.y + x2 * cs.x);
        #pragma unroll
        for (int rr = 0; rr < 4; rr++) {
            int h = kh * 4 + rr;
            *reinterpret_cast<float2*>(
                outk + (((size_t)(b * Hh + h) * Tt + t) * DH + 2 * j)) = r;
        }
    }
    {
        int d = (tid * 4) & 127;
        int kh = tid >> 5;
        float4 v4 = make_float4(vvp[0].x, vvp[0].y, vvp[1].x, vvp[1].y);
        #pragma unroll
        for (int rr = 0; rr < 4; rr++) {
            int h = kh * 4 + rr;
            *reinterpret_cast<float4*>(
                outv + (((size_t)(b * Hh + h) * Tt + t) * DH + d)) = v4;
        }
    }
}

// ---------------------------------------------------------------------------
extern "C" void kernel_launch(void* const* d_in, const int* in_sizes, int n_in,
                              void* d_out, int out_size)
{
    const float* x  = (const float*)d_in[0];
    const float* Wq = (const float*)d_in[1];
    const float* Wk = (const float*)d_in[2];
    const float* Wv = (const float*)d_in[3];
    const float* gq = (const float*)d_in[4];
    const float* gk = (const float*)d_in[5];
    float* out = (float*)d_out;

    cudaFuncSetAttribute(gemm_kernel,
                         cudaFuncAttributeMaxDynamicSharedMemorySize, SMEM_BYTES);

    rope_table_kernel<<<(Tt * 64 + 255) / 256, 256>>>();
    convert_x_kernel<<<(int)(((size_t)Mrows * Kdim / 4 + 255) / 256), 256>>>(x);
    convert_w_kernel<<<dim3(Ncols / 32, Kdim / 32), dim3(32, 8)>>>(Wq, Wk, Wv);
    gemm_kernel<<<MT * NT, 128, SMEM_BYTES>>>();
    epilogue_kernel<<<Mrows, 256>>>(gq, gk, out);
}